// round 16
// baseline (speedup 1.0000x reference)
#include <cuda_runtime.h>
#include <math.h>

#define FULLMASK 0xffffffffu

#define BB 2
#define KK 2048
#define NN 16384
#define SROWS 65536      // B*K*16 sample-rows
#define ROWS 4096        // B*K
#define CBEV 256
#define HBEV 100
#define WBEV 176
#define FEAT_DIM 304
#define OUTC 128

// spatial hash for ball query
#define NXC 89
#define NYC 51
#define NCELL (NXC * NYC)    // 4539 per batch
#define CAP 64

// ---------------- scratch (device globals; no allocs allowed) ----------------
__device__ float4 g_g0[SROWS];            // grouped scale0: (rel xyz, feat)
__device__ float4 g_g1[SROWS];            // grouped scale1
__device__ unsigned char g_e0[ROWS];
__device__ unsigned char g_e1[ROWS];
__device__ float2 g_mm0[ROWS * 16];       // per-(kp,ch) (max,min) of z, scale0
__device__ float2 g_mm1[ROWS * 32];       // scale1
__device__ float g_feats[ROWS * FEAT_DIM];
__device__ float g_fz[ROWS * OUTC];
// one zeroed region: [0:512) acc floats; [512:512+2*NCELL) ccnt ints
__device__ float g_zr[512 + 2 * NCELL];
#define g_acc g_zr
__device__ float4 g_cells[2 * NCELL * CAP];  // (x,y,z,idx-as-int)

// acc layout:
//  [0:14)   s0 grouped moments; [16:30) s1 grouped moments
//  [32:64)  s0 z stats (sum16 @32, sq16 @48)
//  [64:128) s1 z stats (sum32 @64, sq32 @96)
//  [160:288) final sum128 ; [288:416) final sq128

// ---------------- scatter points into 1.6m xy-cells --------------------------
__global__ void k_scatter(const float* __restrict__ pxyz) {
    int* ccnt = (int*)(g_zr + 512);
    int gid = blockIdx.x * 256 + threadIdx.x;     // 32768
    int b = gid >> 14;
    const float* p = pxyz + (size_t)gid * 3;
    float x = p[0], y = p[1], z = p[2];
    int cx = min(max((int)floorf((x + 70.4f) * 0.625f), 0), NXC - 1);
    int cy = min(max((int)floorf((y + 40.0f) * 0.625f), 0), NYC - 1);
    int cell = b * NCELL + cy * NXC + cx;
    int slot = atomicAdd(&ccnt[cell], 1);
    if (slot < CAP)
        g_cells[(size_t)cell * CAP + slot] =
            make_float4(x, y, z, __int_as_float(gid & 16383));
}

// ---------------- ball query + moments, with BEV gather co-resident ----------
// grid = 512 (group warps) + 4096 (bev rows)
__global__ void __launch_bounds__(256) k_group2(
        const float* __restrict__ kp, const float* __restrict__ pxyz,
        const float* __restrict__ pfeat, const float* __restrict__ sf,
        const int* __restrict__ pstride) {
    if (blockIdx.x >= 512) {               // ---- BEV bilinear gather part ----
        int row = blockIdx.x - 512;        // 0..4095
        int b = row >> 11;
        float stride = (float)pstride[0];
        float kx = kp[row * 3 + 0];
        float ky = kp[row * 3 + 1];
        float x = (kx - (-70.4f)) / 0.1f / stride;
        float y = (ky - (-40.0f)) / 0.1f / stride;
        int xi = (int)floorf(x), yi = (int)floorf(y);
        int x0 = min(max(xi, 0), WBEV - 1), x1 = min(max(xi + 1, 0), WBEV - 1);
        int y0 = min(max(yi, 0), HBEV - 1), y1 = min(max(yi + 1, 0), HBEV - 1);
        float x0f = (float)x0, x1f = (float)x1, y0f = (float)y0, y1f = (float)y1;
        float wa = (x1f - x) * (y1f - y);
        float wb = (x1f - x) * (y - y0f);
        float wc = (x - x0f) * (y1f - y);
        float wd = (x - x0f) * (y - y0f);
        const float* base = sf + (size_t)b * CBEV * HBEV * WBEV;
        int c = threadIdx.x;               // 256 threads = channels
        const float* pc = base + (size_t)c * (HBEV * WBEV);
        float Ia = __ldg(pc + y0 * WBEV + x0);
        float Ib = __ldg(pc + y1 * WBEV + x0);
        float Ic = __ldg(pc + y0 * WBEV + x1);
        float Id = __ldg(pc + y1 * WBEV + x1);
        g_feats[row * FEAT_DIM + c] = Ia * wa + Ib * wb + Ic * wc + Id * wd;
        return;
    }
    // ---- ball query part ----
    __shared__ int s_hits[8][32];
    __shared__ int s_cnt[8];
    __shared__ float smA[28];          // [0:14) scale0 moments, [14:28) scale1
    const int* ccnt = (const int*)(g_zr + 512);
    int tid = threadIdx.x;
    int wib = tid >> 5, lane = tid & 31;
    if (tid < 28) smA[tid] = 0.f;
    int kpid = blockIdx.x * 8 + wib;              // 512 CTAs x 8 warps = 4096
    int b = kpid >> 11;
    float kx = kp[kpid * 3 + 0], ky = kp[kpid * 3 + 1], kz = kp[kpid * 3 + 2];
    if (lane == 0) s_cnt[wib] = 0;
    __syncthreads();
    const float R0SQ = (float)(0.4 * 0.4);
    const float R1SQ = (float)(0.8 * 0.8);
    int cx0 = min(max((int)floorf((kx - 0.81f + 70.4f) * 0.625f), 0), NXC - 1);
    int cx1 = min(max((int)floorf((kx + 0.81f + 70.4f) * 0.625f), 0), NXC - 1);
    int cy0 = min(max((int)floorf((ky - 0.81f + 40.0f) * 0.625f), 0), NYC - 1);
    int cy1 = min(max((int)floorf((ky + 0.81f + 40.0f) * 0.625f), 0), NYC - 1);
    for (int cy = cy0; cy <= cy1; cy++) {
        for (int cx = cx0; cx <= cx1; cx++) {
            int cell = b * NCELL + cy * NXC + cx;
            int cnt = min(ccnt[cell], CAP);
            const float4* bp = &g_cells[(size_t)cell * CAP];
            for (int i = lane; i < cnt; i += 32) {
                float4 p = bp[i];
                float dx = kx - p.x, dy = ky - p.y, dz = kz - p.z;
                float d = __fadd_rn(__fadd_rn(__fmul_rn(dx, dx), __fmul_rn(dy, dy)),
                                    __fmul_rn(dz, dz));
                if (d < R1SQ) {
                    int pos = atomicAdd(&s_cnt[wib], 1);
                    if (pos < 32)
                        s_hits[wib][pos] = (__float_as_int(p.w) << 1) | (d < R0SQ ? 1 : 0);
                }
            }
        }
    }
    __syncwarp();
    int cnt = min(s_cnt[wib], 32);
    if (lane == 0 && cnt > 1) {            // insertion sort by (idx<<1|r0) = idx order
        for (int i = 1; i < cnt; i++) {
            int key = s_hits[wib][i];
            int j = i - 1;
            while (j >= 0 && s_hits[wib][j] > key) { s_hits[wib][j + 1] = s_hits[wib][j]; j--; }
            s_hits[wib][j + 1] = key;
        }
    }
    __syncwarp();
    int ent = (lane < cnt) ? s_hits[wib][lane] : 0;
    unsigned mask0 = __ballot_sync(FULLMASK, (lane < cnt) && (ent & 1));
    int n0 = __popc(mask0);
    int scale = (lane < 16) ? 1 : 0;       // lanes 0-15: scale1; 16-31: scale0
    int s = scale ? lane : (lane - 16);
    int myidx = -1;
    if (scale) {
        if (cnt > 0) myidx = ((s < cnt) ? s_hits[wib][s] : s_hits[wib][0]) >> 1;
    } else {
        if (n0 > 0) {
            int target = (s < n0) ? s : 0;
            unsigned m = mask0;
            for (int t = 0; t < target; t++) m &= m - 1;
            int pos = __ffs(m) - 1;
            myidx = s_hits[wib][pos] >> 1;
        }
    }
    float4 out = make_float4(0.f, 0.f, 0.f, 0.f);
    if (myidx >= 0) {
        const float* pp = pxyz + ((size_t)b * NN + myidx) * 3;
        out.x = pp[0] - kx;
        out.y = pp[1] - ky;
        out.z = pp[2] - kz;
        out.w = pfeat[(size_t)b * NN + myidx];
    }
    if (scale) g_g1[(size_t)kpid * 16 + s] = out;
    else       g_g0[(size_t)kpid * 16 + s] = out;
    if (s == 0) {
        if (scale) g_e1[kpid] = (cnt == 0);
        else       g_e0[kpid] = (n0 == 0);
    }
    // fused moments: width-16 shuffle reduce, per-half-warp
    float mm[14];
    mm[0] = out.x; mm[1] = out.y; mm[2] = out.z; mm[3] = out.w;
    mm[4] = out.x * out.x; mm[5] = out.x * out.y; mm[6] = out.x * out.z; mm[7] = out.x * out.w;
    mm[8] = out.y * out.y; mm[9] = out.y * out.z; mm[10] = out.y * out.w;
    mm[11] = out.z * out.z; mm[12] = out.z * out.w; mm[13] = out.w * out.w;
#pragma unroll
    for (int v = 0; v < 14; v++) {
        float val = mm[v];
        val += __shfl_down_sync(FULLMASK, val, 8, 16);
        val += __shfl_down_sync(FULLMASK, val, 4, 16);
        val += __shfl_down_sync(FULLMASK, val, 2, 16);
        val += __shfl_down_sync(FULLMASK, val, 1, 16);
        mm[v] = val;
    }
    if (lane == 16) {          // scale0 totals
#pragma unroll
        for (int v = 0; v < 14; v++) atomicAdd(&smA[v], mm[v]);
    } else if (lane == 0) {    // scale1 totals
#pragma unroll
        for (int v = 0; v < 14; v++) atomicAdd(&smA[14 + v], mm[v]);
    }
    __syncthreads();
    if (tid < 28) atomicAdd(&g_acc[(tid < 14) ? tid : (tid + 2)], smA[tid]);
}

// ---------------- fused MLP + CTA-local z reduce (no z materialization) ------
__global__ void __launch_bounds__(256) k_mlp2(
        const float* __restrict__ W0a, const float* __restrict__ gamma0a,
        const float* __restrict__ beta0a, const float* __restrict__ W1a,
        const float* __restrict__ W0b, const float* __restrict__ gamma0b,
        const float* __restrict__ beta0b, const float* __restrict__ W1b) {
    __shared__ float sW0[64];
    __shared__ float sW1[512];
    __shared__ float sA[16], sB[16];
    __shared__ float s_red[64];
    __shared__ float sZ[256 * 33];            // 256 rows x up to 32 ch, pad 33
    int tid = threadIdx.x;
    int bid = blockIdx.x;                     // 512 blocks: <256 scale0, else scale1
    bool s1 = bid >= 256;
    const float* W0 = s1 ? W0b : W0a;
    const float* W1 = s1 ? W1b : W1a;
    const float* gamma0 = s1 ? gamma0b : gamma0a;
    const float* beta0 = s1 ? beta0b : beta0a;
    int C = s1 ? 32 : 16;
    int momOff = s1 ? 16 : 0;
    if (tid < 64) { sW0[tid] = W0[tid]; s_red[tid] = 0.f; }
    for (int i = tid; i < C * 16; i += 256) sW1[i] = W1[i];
    __syncthreads();
    if (tid < 16) {
        float w0 = sW0[tid * 4 + 0], w1 = sW0[tid * 4 + 1];
        float w2 = sW0[tid * 4 + 2], w3 = sW0[tid * 4 + 3];
        const float* m = &g_acc[momOff];
        float mean = (w0 * m[0] + w1 * m[1] + w2 * m[2] + w3 * m[3]) * (1.0f / 65536.0f);
        float e2 = w0 * w0 * m[4] + w1 * w1 * m[8] + w2 * w2 * m[11] + w3 * w3 * m[13]
                 + 2.f * (w0 * w1 * m[5] + w0 * w2 * m[6] + w0 * w3 * m[7]
                        + w1 * w2 * m[9] + w1 * w3 * m[10] + w2 * w3 * m[12]);
        e2 *= (1.0f / 65536.0f);
        float var = e2 - mean * mean;
        float sc = gamma0[tid] * rsqrtf(var + 1e-5f);
        sA[tid] = sc;
        sB[tid] = beta0[tid] - mean * sc;
    }
    __syncthreads();
    int row = (bid & 255) * 256 + tid;
    float4 g = (s1 ? g_g1 : g_g0)[row];
    float y[16];
#pragma unroll
    for (int o = 0; o < 16; o++) {
        float z = g.x * sW0[o * 4 + 0] + g.y * sW0[o * 4 + 1] +
                  g.z * sW0[o * 4 + 2] + g.w * sW0[o * 4 + 3];
        y[o] = fmaxf(z * sA[o] + sB[o], 0.f);
    }
    int kpbase = (bid & 255) * 16;
    if (!s1) {
#pragma unroll
        for (int o = 0; o < 16; o++) {
            float z = 0.f;
#pragma unroll
            for (int c = 0; c < 16; c++) z += y[c] * sW1[o * 16 + c];
            sZ[tid * 33 + o] = z;
        }
        __syncthreads();
        // thread = (k, o): 16 kp x 16 ch = 256 items
        int k = tid >> 4, o = tid & 15;
        float mx = -3.4e38f, mn = 3.4e38f, sm = 0.f, sq = 0.f;
#pragma unroll
        for (int s = 0; s < 16; s++) {
            float v = sZ[(k * 16 + s) * 33 + o];
            mx = fmaxf(mx, v); mn = fminf(mn, v);
            sm += v; sq += v * v;
        }
        atomicAdd(&s_red[o], sm);
        atomicAdd(&s_red[16 + o], sq);
        g_mm0[(size_t)(kpbase + k) * 16 + o] = make_float2(mx, mn);
        __syncthreads();
        if (tid < 32) atomicAdd(&g_acc[32 + tid], s_red[tid]);
    } else {
#pragma unroll
        for (int o = 0; o < 32; o++) {
            float z = 0.f;
#pragma unroll
            for (int c = 0; c < 16; c++) z += y[c] * sW1[o * 16 + c];
            sZ[tid * 33 + o] = z;
        }
        __syncthreads();
        // 16 kp x 32 ch = 512 items, 2 per thread
#pragma unroll
        for (int half = 0; half < 2; half++) {
            int it = half * 256 + tid;
            int k = it >> 5, o = it & 31;
            float mx = -3.4e38f, mn = 3.4e38f, sm = 0.f, sq = 0.f;
#pragma unroll
            for (int s = 0; s < 16; s++) {
                float v = sZ[(k * 16 + s) * 33 + o];
                mx = fmaxf(mx, v); mn = fminf(mn, v);
                sm += v; sq += v * v;
            }
            atomicAdd(&s_red[o], sm);
            atomicAdd(&s_red[32 + o], sq);
            g_mm1[(size_t)(kpbase + k) * 32 + o] = make_float2(mx, mn);
        }
        __syncthreads();
        if (tid < 64) atomicAdd(&g_acc[64 + tid], s_red[tid]);
    }
}

// ---------------- final GEMM with fused pool prologue + stats ----------------
__global__ void __launch_bounds__(256) k_fgemm(
        const float* __restrict__ Wf,
        const float* __restrict__ g1a, const float* __restrict__ b1a,
        const float* __restrict__ g1b, const float* __restrict__ b1b) {
    __shared__ float sF[32 * FEAT_DIM];          // 38.9 KB
    __shared__ float sS[128], sQ[128];
    __shared__ float sA1[48], sB1[48];
    int tid = threadIdx.x;
    int r0 = blockIdx.x * 32;                    // 128 CTAs
    // bn1 coefficients (48 channels)
    if (tid < 16) {
        int o = tid;
        float mean = g_acc[32 + o] * (1.0f / 65536.0f);
        float var = g_acc[48 + o] * (1.0f / 65536.0f) - mean * mean;
        float a = g1a[o] * rsqrtf(var + 1e-5f);
        sA1[tid] = a;
        sB1[tid] = b1a[o] - mean * a;
    } else if (tid < 48) {
        int o = tid - 16;
        float mean = g_acc[64 + o] * (1.0f / 65536.0f);
        float var = g_acc[96 + o] * (1.0f / 65536.0f) - mean * mean;
        float a = g1b[o] * rsqrtf(var + 1e-5f);
        sA1[tid] = a;
        sB1[tid] = b1b[o] - mean * a;
    }
    // bulk load cols 0..255 (bev part) of 32 rows
    {
        const float4* src = (const float4*)g_feats;
        float4* dst = (float4*)sF;
        for (int i = tid; i < 32 * 64; i += 256) {
            int r = i >> 6, c4 = i & 63;
            dst[r * (FEAT_DIM / 4) + c4] = src[(size_t)(r0 + r) * (FEAT_DIM / 4) + c4];
        }
    }
    if (tid < 128) { sS[tid] = 0.f; sQ[tid] = 0.f; }
    __syncthreads();
    // pool fill cols 256..303: 32 rows x 48 ch = 1536 items
    for (int it = tid; it < 1536; it += 256) {
        int r = it / 48, c = it - (it / 48) * 48;
        float2 mm;
        unsigned char e;
        int col;
        if (c < 16) {
            mm = g_mm0[(size_t)(r0 + r) * 16 + c];
            e = g_e0[r0 + r];
            col = 256 + c;
        } else {
            int o = c - 16;
            mm = g_mm1[(size_t)(r0 + r) * 32 + o];
            e = g_e1[r0 + r];
            col = 272 + o;
        }
        float a = sA1[c];
        float v = (a >= 0.f) ? mm.x : mm.y;
        float rr = fmaxf(v * a + sB1[c], 0.f);
        if (e) rr = 0.f;
        sF[r * FEAT_DIM + col] = rr;
    }
    __syncthreads();
    int o = tid & 127;
    int rh = tid >> 7;
    float acc_[16];
#pragma unroll
    for (int r = 0; r < 16; r++) acc_[r] = 0.f;
    const float4* wrow = (const float4*)(Wf + (size_t)o * FEAT_DIM);
    const float4* fbase = (const float4*)sF + (size_t)(rh * 16) * (FEAT_DIM / 4);
#pragma unroll 2
    for (int c4 = 0; c4 < FEAT_DIM / 4; c4++) {
        float4 w = __ldg(wrow + c4);
#pragma unroll
        for (int r = 0; r < 16; r++) {
            float4 f = fbase[(size_t)r * (FEAT_DIM / 4) + c4];
            acc_[r] += w.x * f.x + w.y * f.y + w.z * f.z + w.w * f.w;
        }
    }
    float S = 0.f, Q = 0.f;
#pragma unroll
    for (int r = 0; r < 16; r++) {
        float z = acc_[r];
        g_fz[(size_t)(r0 + rh * 16 + r) * OUTC + o] = z;
        S += z; Q += z * z;
    }
    atomicAdd(&sS[o], S);
    atomicAdd(&sQ[o], Q);
    __syncthreads();
    if (tid < 128) {
        atomicAdd(&g_acc[160 + tid], sS[tid]);
        atomicAdd(&g_acc[288 + tid], sQ[tid]);
    }
}

// ---------------- final bn + relu -> d_out (float4) -------------------------
__global__ void k_fbn(const float* __restrict__ gamma, const float* __restrict__ beta,
                      float* __restrict__ out) {
    int gid = blockIdx.x * 256 + threadIdx.x;     // 131072 float4s
    int o4 = (gid & 31) * 4;                      // channel base
    float4 z = ((const float4*)g_fz)[gid];
    float4 r;
    {
        float mean = g_acc[160 + o4 + 0] * (1.0f / 4096.0f);
        float var = g_acc[288 + o4 + 0] * (1.0f / 4096.0f) - mean * mean;
        r.x = fmaxf((z.x - mean) * rsqrtf(var + 1e-5f) * gamma[o4 + 0] + beta[o4 + 0], 0.f);
    }
    {
        float mean = g_acc[160 + o4 + 1] * (1.0f / 4096.0f);
        float var = g_acc[288 + o4 + 1] * (1.0f / 4096.0f) - mean * mean;
        r.y = fmaxf((z.y - mean) * rsqrtf(var + 1e-5f) * gamma[o4 + 1] + beta[o4 + 1], 0.f);
    }
    {
        float mean = g_acc[160 + o4 + 2] * (1.0f / 4096.0f);
        float var = g_acc[288 + o4 + 2] * (1.0f / 4096.0f) - mean * mean;
        r.z = fmaxf((z.z - mean) * rsqrtf(var + 1e-5f) * gamma[o4 + 2] + beta[o4 + 2], 0.f);
    }
    {
        float mean = g_acc[160 + o4 + 3] * (1.0f / 4096.0f);
        float var = g_acc[288 + o4 + 3] * (1.0f / 4096.0f) - mean * mean;
        r.w = fmaxf((z.w - mean) * rsqrtf(var + 1e-5f) * gamma[o4 + 3] + beta[o4 + 3], 0.f);
    }
    ((float4*)out)[gid] = r;
}

// ---------------- launch -----------------------------------------------------
extern "C" void kernel_launch(void* const* d_in, const int* in_sizes, int n_in,
                              void* d_out, int out_size) {
    const float* kp     = (const float*)d_in[0];
    const float* pxyz   = (const float*)d_in[1];
    const float* pfeat  = (const float*)d_in[2];
    const float* sf     = (const float*)d_in[3];
    const int*   stridep= (const int*)d_in[4];
    const float* W0_s0  = (const float*)d_in[5];
    const float* g0_s0  = (const float*)d_in[6];
    const float* b0_s0  = (const float*)d_in[7];
    const float* W1_s0  = (const float*)d_in[8];
    const float* g1_s0  = (const float*)d_in[9];
    const float* b1_s0  = (const float*)d_in[10];
    const float* W0_s1  = (const float*)d_in[11];
    const float* g0_s1  = (const float*)d_in[12];
    const float* b0_s1  = (const float*)d_in[13];
    const float* W1_s1  = (const float*)d_in[14];
    const float* g1_s1  = (const float*)d_in[15];
    const float* b1_s1  = (const float*)d_in[16];
    const float* Wf     = (const float*)d_in[17];
    const float* gf     = (const float*)d_in[18];
    const float* bf     = (const float*)d_in[19];
    (void)in_sizes; (void)n_in; (void)out_size;

    void* zrp; cudaGetSymbolAddress(&zrp, g_zr);
    cudaMemsetAsync(zrp, 0, (512 + 2 * NCELL) * sizeof(float));

    k_scatter<<<128, 256>>>(pxyz);
    k_group2<<<4608, 256>>>(kp, pxyz, pfeat, sf, stridep);

    k_mlp2<<<512, 256>>>(W0_s0, g0_s0, b0_s0, W1_s0, W0_s1, g0_s1, b0_s1, W1_s1);

    k_fgemm<<<128, 256>>>(Wf, g1_s0, b1_s0, g1_s1, b1_s1);
    k_fbn<<<512, 256>>>(gf, bf, (float*)d_out);
}